// round 4
// baseline (speedup 1.0000x reference)
#include <cuda_runtime.h>
#include <cstdint>

#define N_ATOMS_MAX 50000
#define CDIM 64
#define ROW  (3 * CDIM)   // 192 floats per atom

// Scratch accumulator (38.4 MB) — static __device__ per harness rules.
__device__ float g_agg[N_ATOMS_MAX * ROW];

typedef unsigned long long u64;

// ---- packed f32x2 helpers (sm_103a) ---------------------------------------
__device__ __forceinline__ u64 pack2(float a, float b) {
    u64 r; asm("mov.b64 %0, {%1, %2};" : "=l"(r) : "f"(a), "f"(b)); return r;
}
__device__ __forceinline__ void unpack2(u64 v, float& a, float& b) {
    asm("mov.b64 {%0, %1}, %2;" : "=f"(a), "=f"(b) : "l"(v));
}
__device__ __forceinline__ u64 addx2(u64 a, u64 b) {
    u64 r; asm("add.rn.f32x2 %0, %1, %2;" : "=l"(r) : "l"(a), "l"(b)); return r;
}
__device__ __forceinline__ u64 mulx2(u64 a, u64 b) {
    u64 r; asm("mul.rn.f32x2 %0, %1, %2;" : "=l"(r) : "l"(a), "l"(b)); return r;
}

// ---------------------------------------------------------------------------
// Pair kernel: 4 threads per pair, 16 channels per thread.
//   ix[p,x,c] = (p3[j,x,c] + d3[p,x]) * i1[p,c]  --red.add--> g_agg[i,x,c]
// Packed f32x2 math halves FLOP instruction count; vectorized 128-bit loads;
// red.global.add.v4.f32 scatter (no return trip).
// ---------------------------------------------------------------------------
__global__ void __launch_bounds__(256) pair_kernel(
    const int* __restrict__ ind,
    const float* __restrict__ p3,
    const float* __restrict__ i1,
    const float* __restrict__ d3,
    float* __restrict__ agg,
    int n_pairs)
{
    int t = blockIdx.x * blockDim.x + threadIdx.x;
    int pair = t >> 2;
    if (pair >= n_pairs) return;
    int lane = t & 3;                       // 16-channel slice

    int2 idx = *reinterpret_cast<const int2*>(ind + 2 * pair);
    int ai = idx.x;
    int aj = idx.y;

    // gate: 16 channels = 8 x f32x2, loaded as 4 x 128-bit
    const ulonglong2* gi =
        reinterpret_cast<const ulonglong2*>(i1 + (size_t)pair * CDIM + lane * 16);
    u64 g2[8];
    {
        ulonglong2 a0 = gi[0], a1 = gi[1], a2 = gi[2], a3 = gi[3];
        g2[0] = a0.x; g2[1] = a0.y; g2[2] = a1.x; g2[3] = a1.y;
        g2[4] = a2.x; g2[5] = a2.y; g2[6] = a3.x; g2[7] = a3.y;
    }

    float dv0 = d3[3 * pair + 0];
    float dv1 = d3[3 * pair + 1];
    float dv2 = d3[3 * pair + 2];
    u64 dxx[3];
    dxx[0] = pack2(dv0, dv0);
    dxx[1] = pack2(dv1, dv1);
    dxx[2] = pack2(dv2, dv2);

    const ulonglong2* pj =
        reinterpret_cast<const ulonglong2*>(p3 + (size_t)aj * ROW) + lane * 4;
    float* pa = agg + (size_t)ai * ROW + lane * 16;

#pragma unroll
    for (int x = 0; x < 3; x++) {
        u64 d2 = dxx[x];
        ulonglong2 v0 = pj[x * 16 + 0];
        ulonglong2 v1 = pj[x * 16 + 1];
        ulonglong2 v2 = pj[x * 16 + 2];
        ulonglong2 v3 = pj[x * 16 + 3];

        u64 r0 = mulx2(addx2(v0.x, d2), g2[0]);
        u64 r1 = mulx2(addx2(v0.y, d2), g2[1]);
        u64 r2 = mulx2(addx2(v1.x, d2), g2[2]);
        u64 r3 = mulx2(addx2(v1.y, d2), g2[3]);
        u64 r4 = mulx2(addx2(v2.x, d2), g2[4]);
        u64 r5 = mulx2(addx2(v2.y, d2), g2[5]);
        u64 r6 = mulx2(addx2(v3.x, d2), g2[6]);
        u64 r7 = mulx2(addx2(v3.y, d2), g2[7]);

        float f0, f1, f2, f3;
        float* base = pa + x * CDIM;
        unpack2(r0, f0, f1); unpack2(r1, f2, f3);
        asm volatile("red.global.add.v4.f32 [%0], {%1, %2, %3, %4};"
                     :: "l"(base + 0), "f"(f0), "f"(f1), "f"(f2), "f"(f3) : "memory");
        unpack2(r2, f0, f1); unpack2(r3, f2, f3);
        asm volatile("red.global.add.v4.f32 [%0], {%1, %2, %3, %4};"
                     :: "l"(base + 4), "f"(f0), "f"(f1), "f"(f2), "f"(f3) : "memory");
        unpack2(r4, f0, f1); unpack2(r5, f2, f3);
        asm volatile("red.global.add.v4.f32 [%0], {%1, %2, %3, %4};"
                     :: "l"(base + 8), "f"(f0), "f"(f1), "f"(f2), "f"(f3) : "memory");
        unpack2(r6, f0, f1); unpack2(r7, f2, f3);
        asm volatile("red.global.add.v4.f32 [%0], {%1, %2, %3, %4};"
                     :: "l"(base + 12), "f"(f0), "f"(f1), "f"(f2), "f"(f3) : "memory");
    }
}

// ---------------------------------------------------------------------------
// Epilogue: per-atom 3x64 @ 64x64 GEMM + self-dot.
// ---------------------------------------------------------------------------
__global__ void gemm_kernel(const float* __restrict__ agg,
                            const float* __restrict__ W,
                            float* __restrict__ p3_new,
                            float* __restrict__ dotted,
                            int n_atoms)
{
    __shared__ float sWT[CDIM][CDIM + 1];   // sWT[c][d] = W[d,c]
    __shared__ float sA[4][ROW];

    int tid = threadIdx.x;                   // 0..255

    for (int k = tid; k < CDIM * CDIM; k += 256) {
        int d = k >> 6, c = k & 63;
        sWT[c][d] = W[k];
    }

    int a0 = blockIdx.x * 4;
    for (int k = tid; k < 4 * ROW; k += 256) {
        int la = k / ROW;
        int e  = k - la * ROW;
        int a  = a0 + la;
        sA[la][e] = (a < n_atoms) ? agg[(size_t)a * ROW + e] : 0.f;
    }
    __syncthreads();

    int la = tid >> 6;
    int d  = tid & 63;
    int a  = a0 + la;
    if (a >= n_atoms) return;

    float dot = 0.f;
#pragma unroll
    for (int x = 0; x < 3; x++) {
        float s = 0.f;
#pragma unroll
        for (int c = 0; c < CDIM; c++) {
            s += sA[la][x * CDIM + c] * sWT[c][d];
        }
        p3_new[(size_t)a * ROW + x * CDIM + d] = s;
        dot += s * s;
    }
    dotted[(size_t)a * CDIM + d] = dot;
}

// ---------------------------------------------------------------------------
// Inputs (metadata order): ind_2 [P,2] i32, p3 [A,3,64] f32, i1 [P,64] f32,
// d3 [P,3] f32, W [64,64] f32.  Output: p3_new [A,3,64] ++ dotted [A,64].
// ---------------------------------------------------------------------------
extern "C" void kernel_launch(void* const* d_in, const int* in_sizes, int n_in,
                              void* d_out, int out_size)
{
    const int*   ind = (const int*)  d_in[0];
    const float* p3  = (const float*)d_in[1];
    const float* i1  = (const float*)d_in[2];
    const float* d3  = (const float*)d_in[3];
    const float* W   = (const float*)d_in[4];

    int n_pairs = in_sizes[0] / 2;
    int n_atoms = in_sizes[1] / ROW;

    float* p3_new = (float*)d_out;
    float* dotted = (float*)d_out + (size_t)n_atoms * ROW;

    float* agg;
    cudaGetSymbolAddress((void**)&agg, g_agg);

    // 1) zero accumulator via memset node (cheaper than a kernel)
    cudaMemsetAsync(agg, 0, (size_t)n_atoms * ROW * sizeof(float));

    // 2) pair scatter-reduce: 4 threads per pair
    {
        int total = n_pairs * 4;
        int blk = 256;
        pair_kernel<<<(total + blk - 1) / blk, blk>>>(ind, p3, i1, d3, agg, n_pairs);
    }

    // 3) epilogue GEMM + dot
    {
        int blocks = (n_atoms + 3) / 4;
        gemm_kernel<<<blocks, 256>>>(agg, W, p3_new, dotted, n_atoms);
    }
}

// round 7
// speedup vs baseline: 1.4869x; 1.4869x over previous
#include <cuda_runtime.h>
#include <cstdint>

#define N_ATOMS_MAX 50000
#define CDIM 64
#define ROW  (3 * CDIM)   // 192 floats per atom

// Scratch accumulator (38.4 MB) — static __device__ per harness rules.
__device__ float g_agg[N_ATOMS_MAX * ROW];

typedef unsigned long long u64;

// ---- packed f32x2 helpers (sm_103a) ---------------------------------------
__device__ __forceinline__ u64 pack2(float a, float b) {
    u64 r; asm("mov.b64 %0, {%1, %2};" : "=l"(r) : "f"(a), "f"(b)); return r;
}
__device__ __forceinline__ void unpack2(u64 v, float& a, float& b) {
    asm("mov.b64 {%0, %1}, %2;" : "=f"(a), "=f"(b) : "l"(v));
}
__device__ __forceinline__ u64 fma2(u64 a, u64 b, u64 c) {
    u64 r; asm("fma.rn.f32x2 %0, %1, %2, %3;" : "=l"(r) : "l"(a), "l"(b), "l"(c)); return r;
}

// ---------------------------------------------------------------------------
// Pair kernel (reverted to R1 shape — it sits at the L2-traffic floor).
// 16 threads per pair; each thread owns 4 channels (float4).
//   ix[p,x,c] = (p3[j,x,c] + d3[p,x]) * i1[p,c]  --red.add--> g_agg[i,x,c]
// ---------------------------------------------------------------------------
__global__ void pair_kernel(const int* __restrict__ ind,
                            const float* __restrict__ p3,
                            const float* __restrict__ i1,
                            const float* __restrict__ d3,
                            float* __restrict__ agg,
                            int n_pairs)
{
    int t = blockIdx.x * blockDim.x + threadIdx.x;
    int pair = t >> 4;
    if (pair >= n_pairs) return;
    int lane = t & 15;                   // channel group: 4 channels each

    int ai = ind[2 * pair + 0];          // destination atom i
    int aj = ind[2 * pair + 1];          // source atom j

    float4 g = *reinterpret_cast<const float4*>(i1 + (size_t)pair * CDIM + lane * 4);

    float dv[3];
    dv[0] = d3[3 * pair + 0];
    dv[1] = d3[3 * pair + 1];
    dv[2] = d3[3 * pair + 2];

    const float4* pj = reinterpret_cast<const float4*>(p3 + (size_t)aj * ROW);
    float4*       pa = reinterpret_cast<float4*>(agg + (size_t)ai * ROW);

#pragma unroll
    for (int x = 0; x < 3; x++) {
        float4 v = pj[x * 16 + lane];
        float dx = dv[x];
        float r0 = (v.x + dx) * g.x;
        float r1 = (v.y + dx) * g.y;
        float r2 = (v.z + dx) * g.z;
        float r3 = (v.w + dx) * g.w;
        asm volatile("red.global.add.v4.f32 [%0], {%1, %2, %3, %4};"
                     :: "l"(pa + x * 16 + lane),
                        "f"(r0), "f"(r1), "f"(r2), "f"(r3)
                     : "memory");
    }
}

// ---------------------------------------------------------------------------
// Epilogue v2: register-tiled GEMM + self-dot.
//   p3_new[a,x,d] = sum_c agg[a,x,c] * W[d,c];  dotted[a,d] = sum_x p3_new^2
// Block: 256 threads, 32 atoms. Thread tile: 8 d's (4 f32x2 regs) x 3 rows.
// Per c-iter: 4x LDS.64 (w) + 3x broadcast LDS.32 (sA) -> 12 FFMA2.
// ---------------------------------------------------------------------------
#define ATOMS_PER_BLOCK 32

__global__ void __launch_bounds__(256) gemm_kernel(
    const float* __restrict__ agg,
    const float* __restrict__ W,
    float* __restrict__ p3_new,
    float* __restrict__ dotted,
    int n_atoms)
{
    __shared__ float sWT[CDIM][CDIM + 2];             // sWT[c][d]=W[d,c]; stride 66 (8B-aligned)
    __shared__ float sA[ATOMS_PER_BLOCK][ROW + 4];    // stride 196: atoms land in distinct banks

    int tid = threadIdx.x;           // 0..255
    int a0  = blockIdx.x * ATOMS_PER_BLOCK;

    // stage W transposed
    for (int k = tid; k < CDIM * CDIM; k += 256) {
        int d = k >> 6, c = k & 63;
        sWT[c][d] = W[k];
    }

    // stage 32 agg rows (float4)
    {
        const float4* src = reinterpret_cast<const float4*>(agg);
        for (int k = tid; k < ATOMS_PER_BLOCK * (ROW / 4); k += 256) {
            int la = k / (ROW / 4);
            int e4 = k - la * (ROW / 4);
            int a  = a0 + la;
            float4 v = (a < n_atoms) ? src[(size_t)a * (ROW / 4) + e4]
                                     : make_float4(0.f, 0.f, 0.f, 0.f);
            *reinterpret_cast<float4*>(&sA[la][e4 * 4]) = v;
        }
    }
    __syncthreads();

    int la = tid >> 3;               // local atom 0..31
    int d0 = (tid & 7) * 8;          // this thread's 8 output channels
    int a  = a0 + la;

    u64 acc[3][4];
#pragma unroll
    for (int x = 0; x < 3; x++)
#pragma unroll
        for (int k = 0; k < 4; k++) acc[x][k] = 0ull;

#pragma unroll 8
    for (int c = 0; c < CDIM; c++) {
        const u64* wrow = reinterpret_cast<const u64*>(&sWT[c][d0]);
        u64 w0 = wrow[0], w1 = wrow[1], w2 = wrow[2], w3 = wrow[3];

        float av0 = sA[la][c];
        float av1 = sA[la][CDIM + c];
        float av2 = sA[la][2 * CDIM + c];
        u64 aa0 = pack2(av0, av0);
        u64 aa1 = pack2(av1, av1);
        u64 aa2 = pack2(av2, av2);

        acc[0][0] = fma2(aa0, w0, acc[0][0]);
        acc[0][1] = fma2(aa0, w1, acc[0][1]);
        acc[0][2] = fma2(aa0, w2, acc[0][2]);
        acc[0][3] = fma2(aa0, w3, acc[0][3]);
        acc[1][0] = fma2(aa1, w0, acc[1][0]);
        acc[1][1] = fma2(aa1, w1, acc[1][1]);
        acc[1][2] = fma2(aa1, w2, acc[1][2]);
        acc[1][3] = fma2(aa1, w3, acc[1][3]);
        acc[2][0] = fma2(aa2, w0, acc[2][0]);
        acc[2][1] = fma2(aa2, w1, acc[2][1]);
        acc[2][2] = fma2(aa2, w2, acc[2][2]);
        acc[2][3] = fma2(aa2, w3, acc[2][3]);
    }

    if (a >= n_atoms) return;

    float dot[8];
#pragma unroll
    for (int k = 0; k < 8; k++) dot[k] = 0.f;

#pragma unroll
    for (int x = 0; x < 3; x++) {
        float s[8];
#pragma unroll
        for (int k = 0; k < 4; k++) {
            unpack2(acc[x][k], s[2 * k], s[2 * k + 1]);
            dot[2 * k]     += s[2 * k]     * s[2 * k];
            dot[2 * k + 1] += s[2 * k + 1] * s[2 * k + 1];
        }
        float* out = p3_new + (size_t)a * ROW + x * CDIM + d0;
        *reinterpret_cast<float4*>(out)     = make_float4(s[0], s[1], s[2], s[3]);
        *reinterpret_cast<float4*>(out + 4) = make_float4(s[4], s[5], s[6], s[7]);
    }
    {
        float* out = dotted + (size_t)a * CDIM + d0;
        *reinterpret_cast<float4*>(out)     = make_float4(dot[0], dot[1], dot[2], dot[3]);
        *reinterpret_cast<float4*>(out + 4) = make_float4(dot[4], dot[5], dot[6], dot[7]);
    }
}

// ---------------------------------------------------------------------------
// Inputs (metadata order): ind_2 [P,2] i32, p3 [A,3,64] f32, i1 [P,64] f32,
// d3 [P,3] f32, W [64,64] f32.  Output: p3_new [A,3,64] ++ dotted [A,64].
// ---------------------------------------------------------------------------
extern "C" void kernel_launch(void* const* d_in, const int* in_sizes, int n_in,
                              void* d_out, int out_size)
{
    const int*   ind = (const int*)  d_in[0];
    const float* p3  = (const float*)d_in[1];
    const float* i1  = (const float*)d_in[2];
    const float* d3  = (const float*)d_in[3];
    const float* W   = (const float*)d_in[4];

    int n_pairs = in_sizes[0] / 2;
    int n_atoms = in_sizes[1] / ROW;

    float* p3_new = (float*)d_out;
    float* dotted = (float*)d_out + (size_t)n_atoms * ROW;

    float* agg;
    cudaGetSymbolAddress((void**)&agg, g_agg);

    // 1) zero accumulator
    cudaMemsetAsync(agg, 0, (size_t)n_atoms * ROW * sizeof(float));

    // 2) pair scatter-reduce: 16 threads per pair
    {
        int total = n_pairs * 16;
        int blk = 256;
        pair_kernel<<<(total + blk - 1) / blk, blk>>>(ind, p3, i1, d3, agg, n_pairs);
    }

    // 3) epilogue GEMM + dot
    {
        int blocks = (n_atoms + ATOMS_PER_BLOCK - 1) / ATOMS_PER_BLOCK;
        gemm_kernel<<<blocks, 256>>>(agg, W, p3_new, dotted, n_atoms);
    }
}